// round 4
// baseline (speedup 1.0000x reference)
#include <cuda_runtime.h>

typedef unsigned long long u64;

// ---------- f32x2 packed helpers (Blackwell sm_103a) ----------
__device__ __forceinline__ u64 pk2(float lo, float hi) {
    u64 r; asm("mov.b64 %0,{%1,%2};" : "=l"(r) : "f"(lo), "f"(hi)); return r;
}
__device__ __forceinline__ void unpk2(u64 v, float& lo, float& hi) {
    asm("mov.b64 {%0,%1},%2;" : "=f"(lo), "=f"(hi) : "l"(v));
}
__device__ __forceinline__ u64 fma2(u64 a, u64 b, u64 c) {
    u64 d; asm("fma.rn.f32x2 %0,%1,%2,%3;" : "=l"(d) : "l"(a), "l"(b), "l"(c)); return d;
}
__device__ __forceinline__ u64 add2(u64 a, u64 b) {
    u64 d; asm("add.rn.f32x2 %0,%1,%2;" : "=l"(d) : "l"(a), "l"(b)); return d;
}
__device__ __forceinline__ u64 mul2(u64 a, u64 b) {
    u64 d; asm("mul.rn.f32x2 %0,%1,%2;" : "=l"(d) : "l"(a), "l"(b)); return d;
}

// ---------- activations from PRE-SCALED inputs (scales folded into weights) ----
// sigS(s) = sigmoid(x) where s = -log2(e)*x
// tanhS(s) = tanh(x)   where s = -2*log2(e)*x
__device__ __forceinline__ float ex2a(float x) {
    float y; asm("ex2.approx.f32 %0,%1;" : "=f"(y) : "f"(x)); return y;
}
__device__ __forceinline__ float rcpa(float x) {
    float y; asm("rcp.approx.f32 %0,%1;" : "=f"(y) : "f"(x)); return y;
}
__device__ __forceinline__ float sigS(float s)  { return rcpa(1.0f + ex2a(s)); }
__device__ __forceinline__ float tanhS(float s) { return fmaf(2.0f, rcpa(1.0f + ex2a(s)), -1.0f); }

#define SSC (-1.4426950408889634f)   /* -log2(e)    : sigmoid pre-scale */
#define TSC (-2.8853900817779268f)   /* -2*log2(e)  : tanh pre-scale    */

// One warp per batch row.
// Lanes 0..19 : layer-1 unit j=lane, gate pairs (i,f) in pass1, (g,o) in pass2,
//               reading the (h,h) smem buffer.
// Lane 20     : layer-2 (i,f) dot over previous-step c1, reading the (c,c) buffer.
// Lane 21     : layer-2 (g,o) dot, same buffer.
// All gate pre-activation scales folded into weights/biases.
__global__ void __launch_bounds__(128)
lstm_warp_kernel(const float* __restrict__ xin,
                 const float* __restrict__ Wih1, const float* __restrict__ Whh1,
                 const float* __restrict__ bih1, const float* __restrict__ bhh1,
                 const float* __restrict__ Wih2, const float* __restrict__ Whh2,
                 const float* __restrict__ bih2, const float* __restrict__ bhh2,
                 float* __restrict__ out, int B, int T, int F)
{
    const int w    = threadIdx.x >> 5;
    const int lane = threadIdx.x & 31;
    const int b    = blockIdx.x * 4 + w;

    __shared__ __align__(16) u64 hbuf[4][2][32];   // (h1,h1) duplicated per unit
    __shared__ __align__(16) u64 cbuf[4][2][32];   // (c1,c1) duplicated per unit

    if (b >= B) return;

    // ---- per-lane prescaled weights ----
    u64 wif[20], wgo[20], wxif = 0, wxgo = 0, bif = 0, bgo = 0;
#pragma unroll
    for (int k = 0; k < 20; k++) { wif[k] = 0ull; wgo[k] = 0ull; }

    if (lane < 20) {
        const int j = lane;
#pragma unroll
        for (int k = 0; k < 20; k++) {
            wif[k] = pk2(SSC * Whh1[j * 20 + k],        SSC * Whh1[(20 + j) * 20 + k]);
            wgo[k] = pk2(TSC * Whh1[(40 + j) * 20 + k], SSC * Whh1[(60 + j) * 20 + k]);
        }
        wxif = pk2(SSC * Wih1[j],      SSC * Wih1[20 + j]);
        wxgo = pk2(TSC * Wih1[40 + j], SSC * Wih1[60 + j]);
        bif  = pk2(SSC * (bih1[j] + bhh1[j]),           SSC * (bih1[20 + j] + bhh1[20 + j]));
        bgo  = pk2(TSC * (bih1[40 + j] + bhh1[40 + j]), SSC * (bih1[60 + j] + bhh1[60 + j]));
    } else if (lane == 20) {
#pragma unroll
        for (int k = 0; k < 20; k++)
            wif[k] = pk2(SSC * Wih2[k], SSC * Wih2[20 + k]);
        bif = pk2(SSC * (bih2[0] + bhh2[0]), SSC * (bih2[1] + bhh2[1]));
    } else if (lane == 21) {
#pragma unroll
        for (int k = 0; k < 20; k++)
            wif[k] = pk2(TSC * Wih2[40 + k], SSC * Wih2[60 + k]);
        bif = pk2(TSC * (bih2[2] + bhh2[2]), SSC * (bih2[3] + bhh2[3]));
    }

    const u64 wh2if = pk2(SSC * Whh2[0], SSC * Whh2[1]);   // h2-recurrent, prescaled
    const u64 wh2go = pk2(TSC * Whh2[2], SSC * Whh2[3]);

    // per-lane smem view: L1 lanes see h-buffer, L2 lanes see c-buffer
    const ulonglong2* vb[2] = {
        (const ulonglong2*)((lane < 20) ? hbuf[w][0] : cbuf[w][0]),
        (const ulonglong2*)((lane < 20) ? hbuf[w][1] : cbuf[w][1])
    };
    u64* hst[2] = { hbuf[w][0], hbuf[w][1] };
    u64* cst[2] = { cbuf[w][0], cbuf[w][1] };

    // ---- state ----
    float c1 = 0.0f, c2 = 0.0f, h2 = 0.0f;
    int p = 0;
    hbuf[w][0][lane] = 0ull;
    cbuf[w][0][lane] = 0ull;

    // fused dual-GEMV pass: L1 gates (lanes 0-19) + L2 gates (lanes 20-21)
    auto passes = [&](float x, u64& aif, u64& ago) {
        __syncwarp();                           // orders prev STS before LDS
        const ulonglong2* hp = vb[p];
        const ulonglong2 v0 = hp[0], v1 = hp[1], v2 = hp[2], v3 = hp[3], v4 = hp[4];
        const u64 xx = pk2(x, x);
        u64 aA = fma2(wif[0], v0.x, fma2(wxif, xx, bif));
        u64 gA = fma2(wgo[0], v0.x, fma2(wxgo, xx, bgo));
        u64 aB = mul2(wif[1], v0.y);
        u64 gB = mul2(wgo[1], v0.y);
        aA = fma2(wif[2], v1.x, aA);  gA = fma2(wgo[2], v1.x, gA);
        aB = fma2(wif[3], v1.y, aB);  gB = fma2(wgo[3], v1.y, gB);
        aA = fma2(wif[4], v2.x, aA);  gA = fma2(wgo[4], v2.x, gA);
        aB = fma2(wif[5], v2.y, aB);  gB = fma2(wgo[5], v2.y, gB);
        aA = fma2(wif[6], v3.x, aA);  gA = fma2(wgo[6], v3.x, gA);
        aB = fma2(wif[7], v3.y, aB);  gB = fma2(wgo[7], v3.y, gB);
        aA = fma2(wif[8], v4.x, aA);  gA = fma2(wgo[8], v4.x, gA);
        aB = fma2(wif[9], v4.y, aB);  gB = fma2(wgo[9], v4.y, gB);
        const ulonglong2 v5 = hp[5], v6 = hp[6], v7 = hp[7], v8 = hp[8], v9 = hp[9];
        aA = fma2(wif[10], v5.x, aA); gA = fma2(wgo[10], v5.x, gA);
        aB = fma2(wif[11], v5.y, aB); gB = fma2(wgo[11], v5.y, gB);
        aA = fma2(wif[12], v6.x, aA); gA = fma2(wgo[12], v6.x, gA);
        aB = fma2(wif[13], v6.y, aB); gB = fma2(wgo[13], v6.y, gB);
        aA = fma2(wif[14], v7.x, aA); gA = fma2(wgo[14], v7.x, gA);
        aB = fma2(wif[15], v7.y, aB); gB = fma2(wgo[15], v7.y, gB);
        aA = fma2(wif[16], v8.x, aA); gA = fma2(wgo[16], v8.x, gA);
        aB = fma2(wif[17], v8.y, aB); gB = fma2(wgo[17], v8.y, gB);
        aA = fma2(wif[18], v9.x, aA); gA = fma2(wgo[18], v9.x, gA);
        aB = fma2(wif[19], v9.y, aB); gB = fma2(wgo[19], v9.y, gB);
        aif = add2(aA, aB);
        ago = add2(gA, gB);
    };

    // layer-1 nonlinearity + state update + store (loop-carried critical path)
    auto l1upd = [&](u64 aif, u64 ago) {
        float is, fs, gs, os;
        unpk2(aif, is, fs); unpk2(ago, gs, os);
        const float si = sigS(is), sf = sigS(fs), tg = tanhS(gs), so = sigS(os);
        c1 = fmaf(sf, c1, si * tg);
        const float h1 = so * tanhS(c1 * TSC);
        hst[p ^ 1][lane] = pk2(h1, h1);
        cst[p ^ 1][lane] = pk2(c1, c1);
        p ^= 1;
    };

    // layer-2 nonlinearity + state update (lane 20 holds real values)
    auto l2upd = [&](u64 aif, u64 sh) {
        const u64 hh  = pk2(h2, h2);
        const u64 own = fma2(wh2if, hh, aif);   // (i,f)+h2 terms   [lane 20]
        const u64 oth = fma2(wh2go, hh, sh);    // (g,o)+h2 terms   [lane 21's pair]
        float i2, f2, g2, o2;
        unpk2(own, i2, f2); unpk2(oth, g2, o2);
        const float s2i = sigS(i2), s2f = sigS(f2), t2g = tanhS(g2), s2o = sigS(o2);
        c2 = fmaf(s2f, c2, s2i * t2g);
        h2 = s2o * tanhS(c2 * TSC);
    };

    const float* xrow = xin + (size_t)b * T;
    float*       orow = out + (size_t)b * (T + F);

    u64 aif, ago;

    // ---- peel t = 0: layer-1 only (no phantom layer-2) ----
    passes(__ldg(xrow), aif, ago);
    l1upd(aif, ago);

    // ---- main loop: fused L1(t) + L2(t-1) ----
#pragma unroll 1
    for (int t = 1; t < T; t++) {
        const float x = __ldg(xrow + t);
        passes(x, aif, ago);
        const u64 sh = __shfl_xor_sync(0xffffffffu, aif, 1);  // lane20 <- lane21 (g,o)
        l1upd(aif, ago);          // critical path first
        l2upd(aif, sh);           // off-chain, fills MUFU/FMA slack
        if (lane == 20) orow[t - 1] = c2;
    }

    // ---- flush: layer-2 for step T-1 ----
    passes(0.0f, aif, ago);       // reads c1(T-1) in lanes 20/21; no state change
    {
        const u64 sh = __shfl_xor_sync(0xffffffffu, aif, 1);
        l2upd(aif, sh);
        if (lane == 20) orow[T - 1] = c2;
    }

    // ---- autoregressive future: sequential (x_t = c2 of full previous step) ----
    float c2b = __shfl_sync(0xffffffffu, c2, 20);
#pragma unroll 1
    for (int f = 0; f < F; f++) {
        passes(c2b, aif, ago);    // L1(f); lanes 20/21 output here is stale -> ignored
        l1upd(aif, ago);
        passes(0.0f, aif, ago);   // fresh L2 dot over c1(f)
        const u64 sh = __shfl_xor_sync(0xffffffffu, aif, 1);
        l2upd(aif, sh);
        c2b = __shfl_sync(0xffffffffu, c2, 20);
        if (lane == 20) orow[T + f] = c2;
    }
}

extern "C" void kernel_launch(void* const* d_in, const int* in_sizes, int n_in,
                              void* d_out, int out_size)
{
    const float* xin  = (const float*)d_in[0];
    const float* Wih1 = (const float*)d_in[1];
    const float* Whh1 = (const float*)d_in[2];
    const float* bih1 = (const float*)d_in[3];
    const float* bhh1 = (const float*)d_in[4];
    const float* Wih2 = (const float*)d_in[5];
    const float* Whh2 = (const float*)d_in[6];
    const float* bih2 = (const float*)d_in[7];
    const float* bhh2 = (const float*)d_in[8];

    const int B = 1024;
    const int T = in_sizes[0] / B;          // 4096
    const int F = out_size / B - T;         // 16

    dim3 grid((B + 3) / 4), block(128);
    lstm_warp_kernel<<<grid, block>>>(xin, Wih1, Whh1, bih1, bhh1,
                                      Wih2, Whh2, bih2, bhh2,
                                      (float*)d_out, B, T, F);
}

// round 5
// speedup vs baseline: 1.2618x; 1.2618x over previous
#include <cuda_runtime.h>

typedef unsigned long long u64;

// ---------- f32x2 packed helpers (Blackwell sm_103a) ----------
__device__ __forceinline__ u64 pk2(float lo, float hi) {
    u64 r; asm("mov.b64 %0,{%1,%2};" : "=l"(r) : "f"(lo), "f"(hi)); return r;
}
__device__ __forceinline__ void unpk2(u64 v, float& lo, float& hi) {
    asm("mov.b64 {%0,%1},%2;" : "=f"(lo), "=f"(hi) : "l"(v));
}
__device__ __forceinline__ u64 fma2(u64 a, u64 b, u64 c) {
    u64 d; asm("fma.rn.f32x2 %0,%1,%2,%3;" : "=l"(d) : "l"(a), "l"(b), "l"(c)); return d;
}
__device__ __forceinline__ u64 add2(u64 a, u64 b) {
    u64 d; asm("add.rn.f32x2 %0,%1,%2;" : "=l"(d) : "l"(a), "l"(b)); return d;
}
__device__ __forceinline__ u64 mul2(u64 a, u64 b) {
    u64 d; asm("mul.rn.f32x2 %0,%1,%2;" : "=l"(d) : "l"(a), "l"(b)); return d;
}
__device__ __forceinline__ u64 shfl64(u64 v, int m) {
    return __shfl_xor_sync(0xffffffffu, v, m);
}

// ---------- activations from PRE-SCALED inputs ----------
// sigS(s)  = sigmoid(x), s = -log2(e)*x
// tanhS(s) = tanh(x),    s = -2*log2(e)*x
__device__ __forceinline__ float ex2a(float x) {
    float y; asm("ex2.approx.f32 %0,%1;" : "=f"(y) : "f"(x)); return y;
}
__device__ __forceinline__ float rcpa(float x) {
    float y; asm("rcp.approx.f32 %0,%1;" : "=f"(y) : "f"(x)); return y;
}
__device__ __forceinline__ float sigS(float s)  { return rcpa(1.0f + ex2a(s)); }
__device__ __forceinline__ float tanhS(float s) { return fmaf(2.0f, rcpa(1.0f + ex2a(s)), -1.0f); }

#define SSC (-1.4426950408889634f)   /* -log2(e)   */
#define TSC (-2.8853900817779268f)   /* -2*log2(e) */

// One warp per batch row; lane j (<20) owns layer-1 unit j, gate pairs packed
// f32x2 as (i,f),(g,o). Layer-2 butterfly manually interleaved with the layer-1
// dot so its SHFL latency hides under independent FMAs (ptxas preserves source
// order across sync instructions; R3 lost this overlap).
__global__ void __launch_bounds__(128)
lstm_warp_kernel(const float* __restrict__ xin,
                 const float* __restrict__ Wih1, const float* __restrict__ Whh1,
                 const float* __restrict__ bih1, const float* __restrict__ bhh1,
                 const float* __restrict__ Wih2, const float* __restrict__ Whh2,
                 const float* __restrict__ bih2, const float* __restrict__ bhh2,
                 float* __restrict__ out, int B, int T, int F)
{
    const int w    = threadIdx.x >> 5;
    const int lane = threadIdx.x & 31;
    const int b    = blockIdx.x * 4 + w;

    __shared__ __align__(16) u64 hbuf[4][2][32];   // (h1,h1) duplicated per unit

    if (b >= B) return;

    // ---- per-lane prescaled layer-1 weights (lanes >=20 mirror harmlessly) ----
    const int jj = (lane < 20) ? lane : (lane - 20);

    u64 wif[20], wgo[20];
#pragma unroll
    for (int k = 0; k < 20; k++) {
        wif[k] = pk2(SSC * Whh1[jj * 20 + k],        SSC * Whh1[(20 + jj) * 20 + k]);
        wgo[k] = pk2(TSC * Whh1[(40 + jj) * 20 + k], SSC * Whh1[(60 + jj) * 20 + k]);
    }
    const u64 wxif = pk2(SSC * Wih1[jj],      SSC * Wih1[20 + jj]);
    const u64 wxgo = pk2(TSC * Wih1[40 + jj], SSC * Wih1[60 + jj]);
    const u64 bif  = pk2(SSC * (bih1[jj] + bhh1[jj]),
                         SSC * (bih1[20 + jj] + bhh1[20 + jj]));
    const u64 bgo  = pk2(TSC * (bih1[40 + jj] + bhh1[40 + jj]),
                         SSC * (bih1[60 + jj] + bhh1[60 + jj]));

    // ---- layer-2 prescaled (zero on lanes >=20 -> exact butterfly) ----
    u64 uif = 0ull, ugo = 0ull;
    if (lane < 20) {
        uif = pk2(SSC * Wih2[lane],      SSC * Wih2[20 + lane]);
        ugo = pk2(TSC * Wih2[40 + lane], SSC * Wih2[60 + lane]);
    }
    const u64 wh2if = pk2(SSC * Whh2[0], SSC * Whh2[1]);
    const u64 wh2go = pk2(TSC * Whh2[2], SSC * Whh2[3]);
    const u64 b2if  = pk2(SSC * (bih2[0] + bhh2[0]), SSC * (bih2[1] + bhh2[1]));
    const u64 b2go  = pk2(TSC * (bih2[2] + bhh2[2]), SSC * (bih2[3] + bhh2[3]));

    // ---- state ----
    float c1 = 0.0f, c1p = 0.0f, c2 = 0.0f, h2 = 0.0f;
    int p = 0;
    hbuf[w][0][lane] = 0ull;

    // ---- layer-1-only step (peel / future phase) ----
    auto step_l1 = [&](float x) {
        __syncwarp();
        const ulonglong2* hp = (const ulonglong2*)hbuf[w][p];
        const ulonglong2 v0 = hp[0], v1 = hp[1], v2 = hp[2], v3 = hp[3], v4 = hp[4];
        const u64 xx = pk2(x, x);
        u64 aA = fma2(wif[0], v0.x, fma2(wxif, xx, bif));
        u64 gA = fma2(wgo[0], v0.x, fma2(wxgo, xx, bgo));
        u64 aB = mul2(wif[1], v0.y), gB = mul2(wgo[1], v0.y);
        aA = fma2(wif[2], v1.x, aA);  gA = fma2(wgo[2], v1.x, gA);
        aB = fma2(wif[3], v1.y, aB);  gB = fma2(wgo[3], v1.y, gB);
        aA = fma2(wif[4], v2.x, aA);  gA = fma2(wgo[4], v2.x, gA);
        aB = fma2(wif[5], v2.y, aB);  gB = fma2(wgo[5], v2.y, gB);
        aA = fma2(wif[6], v3.x, aA);  gA = fma2(wgo[6], v3.x, gA);
        aB = fma2(wif[7], v3.y, aB);  gB = fma2(wgo[7], v3.y, gB);
        aA = fma2(wif[8], v4.x, aA);  gA = fma2(wgo[8], v4.x, gA);
        aB = fma2(wif[9], v4.y, aB);  gB = fma2(wgo[9], v4.y, gB);
        const ulonglong2 v5 = hp[5], v6 = hp[6], v7 = hp[7], v8 = hp[8], v9 = hp[9];
        aA = fma2(wif[10], v5.x, aA); gA = fma2(wgo[10], v5.x, gA);
        aB = fma2(wif[11], v5.y, aB); gB = fma2(wgo[11], v5.y, gB);
        aA = fma2(wif[12], v6.x, aA); gA = fma2(wgo[12], v6.x, gA);
        aB = fma2(wif[13], v6.y, aB); gB = fma2(wgo[13], v6.y, gB);
        aA = fma2(wif[14], v7.x, aA); gA = fma2(wgo[14], v7.x, gA);
        aB = fma2(wif[15], v7.y, aB); gB = fma2(wgo[15], v7.y, gB);
        aA = fma2(wif[16], v8.x, aA); gA = fma2(wgo[16], v8.x, gA);
        aB = fma2(wif[17], v8.y, aB); gB = fma2(wgo[17], v8.y, gB);
        aA = fma2(wif[18], v9.x, aA); gA = fma2(wgo[18], v9.x, gA);
        aB = fma2(wif[19], v9.y, aB); gB = fma2(wgo[19], v9.y, gB);
        const u64 aif = add2(aA, aB), ago = add2(gA, gB);
        float is, fs, gs, os; unpk2(aif, is, fs); unpk2(ago, gs, os);
        const float si = sigS(is), sf = sigS(fs), tg = tanhS(gs), so = sigS(os);
        c1 = fmaf(sf, c1, si * tg);
        const float h1 = so * tanhS(c1 * TSC);
        hbuf[w][p ^ 1][lane] = pk2(h1, h1);
        p ^= 1;
    };

    // ---- layer-2-only step (flush / future phase), input = per-lane c1v ----
    auto step_l2 = [&](float c1v) {
        const u64 cc = pk2(c1v, c1v);
        u64 pif = mul2(uif, cc), pgo = mul2(ugo, cc);
#pragma unroll
        for (int m = 16; m; m >>= 1) {
            pif = add2(pif, shfl64(pif, m));
            pgo = add2(pgo, shfl64(pgo, m));
        }
        const u64 hh = pk2(h2, h2);
        pif = fma2(wh2if, hh, add2(pif, b2if));
        pgo = fma2(wh2go, hh, add2(pgo, b2go));
        float i2, f2, g2, o2; unpk2(pif, i2, f2); unpk2(pgo, g2, o2);
        const float s2i = sigS(i2), s2f = sigS(f2), t2g = tanhS(g2), s2o = sigS(o2);
        c2 = fmaf(s2f, c2, s2i * t2g);
        h2 = s2o * tanhS(c2 * TSC);
    };

    const float* xrow = xin + (size_t)b * T;
    float*       orow = out + (size_t)b * (T + F);

    // ---- peel t = 0 ----
    float xc = __ldg(xrow);
    float xn = __ldg(xrow + 1);
    step_l1(xc);
    c1p = c1;

    // ---- main loop: L1(t) with L2(t-1) butterfly interleaved at source level ----
#pragma unroll 1
    for (int t = 1; t < T; t++) {
        xc = xn;
        if (t + 1 < T) xn = __ldg(xrow + t + 1);

        // L2 products + first butterfly level: no smem involved -> before sync
        const u64 cc = pk2(c1p, c1p);
        u64 pif = mul2(uif, cc), pgo = mul2(ugo, cc);
        u64 s0 = shfl64(pif, 16), s1 = shfl64(pgo, 16);

        __syncwarp();                      // prev STS -> this LDS
        const ulonglong2* hp = (const ulonglong2*)hbuf[w][p];
        const ulonglong2 v0 = hp[0], v1 = hp[1], v2 = hp[2], v3 = hp[3], v4 = hp[4];
        const u64 xx = pk2(xc, xc);
        u64 aA = fma2(wif[0], v0.x, fma2(wxif, xx, bif));
        u64 gA = fma2(wgo[0], v0.x, fma2(wxgo, xx, bgo));
        u64 aB = mul2(wif[1], v0.y), gB = mul2(wgo[1], v0.y);

        pif = add2(pif, s0); pgo = add2(pgo, s1);
        s0 = shfl64(pif, 8); s1 = shfl64(pgo, 8);
        aA = fma2(wif[2], v1.x, aA);  gA = fma2(wgo[2], v1.x, gA);
        aB = fma2(wif[3], v1.y, aB);  gB = fma2(wgo[3], v1.y, gB);
        aA = fma2(wif[4], v2.x, aA);  gA = fma2(wgo[4], v2.x, gA);

        pif = add2(pif, s0); pgo = add2(pgo, s1);
        s0 = shfl64(pif, 4); s1 = shfl64(pgo, 4);
        aB = fma2(wif[5], v2.y, aB);  gB = fma2(wgo[5], v2.y, gB);
        aA = fma2(wif[6], v3.x, aA);  gA = fma2(wgo[6], v3.x, gA);
        aB = fma2(wif[7], v3.y, aB);  gB = fma2(wgo[7], v3.y, gB);

        pif = add2(pif, s0); pgo = add2(pgo, s1);
        s0 = shfl64(pif, 2); s1 = shfl64(pgo, 2);
        const ulonglong2 v5 = hp[5], v6 = hp[6], v7 = hp[7], v8 = hp[8], v9 = hp[9];
        aA = fma2(wif[8],  v4.x, aA); gA = fma2(wgo[8],  v4.x, gA);
        aB = fma2(wif[9],  v4.y, aB); gB = fma2(wgo[9],  v4.y, gB);
        aA = fma2(wif[10], v5.x, aA); gA = fma2(wgo[10], v5.x, gA);

        pif = add2(pif, s0); pgo = add2(pgo, s1);
        s0 = shfl64(pif, 1); s1 = shfl64(pgo, 1);
        aB = fma2(wif[11], v5.y, aB); gB = fma2(wgo[11], v5.y, gB);
        aA = fma2(wif[12], v6.x, aA); gA = fma2(wgo[12], v6.x, gA);
        aB = fma2(wif[13], v6.y, aB); gB = fma2(wgo[13], v6.y, gB);
        aA = fma2(wif[14], v7.x, aA); gA = fma2(wgo[14], v7.x, gA);
        aB = fma2(wif[15], v7.y, aB); gB = fma2(wgo[15], v7.y, gB);
        aA = fma2(wif[16], v8.x, aA); gA = fma2(wgo[16], v8.x, gA);
        aB = fma2(wif[17], v8.y, aB); gB = fma2(wgo[17], v8.y, gB);
        aA = fma2(wif[18], v9.x, aA); gA = fma2(wgo[18], v9.x, gA);
        aB = fma2(wif[19], v9.y, aB); gB = fma2(wgo[19], v9.y, gB);

        pif = add2(pif, s0); pgo = add2(pgo, s1);       // butterfly complete
        const u64 hh = pk2(h2, h2);
        pif = fma2(wh2if, hh, add2(pif, b2if));
        pgo = fma2(wh2go, hh, add2(pgo, b2go));

        const u64 aif = add2(aA, aB), ago = add2(gA, gB);

        // ---- all 8 gate activations batched (L1 + L2) ----
        float is, fs, gs, os; unpk2(aif, is, fs); unpk2(ago, gs, os);
        float i2, f2, g2, o2; unpk2(pif, i2, f2); unpk2(pgo, g2, o2);
        const float ei  = ex2a(is), ef  = ex2a(fs), eg  = ex2a(gs), eo  = ex2a(os);
        const float e2i = ex2a(i2), e2f = ex2a(f2), e2g = ex2a(g2), e2o = ex2a(o2);
        const float si  = rcpa(1.0f + ei),  sf  = rcpa(1.0f + ef);
        const float tg  = fmaf(2.0f, rcpa(1.0f + eg), -1.0f);
        const float so  = rcpa(1.0f + eo);
        const float s2i = rcpa(1.0f + e2i), s2f = rcpa(1.0f + e2f);
        const float t2g = fmaf(2.0f, rcpa(1.0f + e2g), -1.0f);
        const float s2o = rcpa(1.0f + e2o);

        c1 = fmaf(sf, c1, si * tg);
        c2 = fmaf(s2f, c2, s2i * t2g);
        const float h1 = so  * tanhS(c1 * TSC);
        h2             = s2o * tanhS(c2 * TSC);

        hbuf[w][p ^ 1][lane] = pk2(h1, h1);
        p ^= 1;
        c1p = c1;
        if (lane == 0) orow[t - 1] = c2;
    }

    // ---- flush: L2 for step T-1 ----
    step_l2(c1p);
    if (lane == 0) orow[T - 1] = c2;

    // ---- autoregressive future: strictly sequential ----
    float c2b = __shfl_sync(0xffffffffu, c2, 0);
#pragma unroll 1
    for (int f = 0; f < F; f++) {
        step_l1(c2b);
        step_l2(c1);
        c2b = __shfl_sync(0xffffffffu, c2, 0);
        if (lane == 0) orow[T + f] = c2;
    }
}

extern "C" void kernel_launch(void* const* d_in, const int* in_sizes, int n_in,
                              void* d_out, int out_size)
{
    const float* xin  = (const float*)d_in[0];
    const float* Wih1 = (const float*)d_in[1];
    const float* Whh1 = (const float*)d_in[2];
    const float* bih1 = (const float*)d_in[3];
    const float* bhh1 = (const float*)d_in[4];
    const float* Wih2 = (const float*)d_in[5];
    const float* Whh2 = (const float*)d_in[6];
    const float* bih2 = (const float*)d_in[7];
    const float* bhh2 = (const float*)d_in[8];

    const int B = 1024;
    const int T = in_sizes[0] / B;          // 4096
    const int F = out_size / B - T;         // 16

    dim3 grid((B + 3) / 4), block(128);
    lstm_warp_kernel<<<grid, block>>>(xin, Wih1, Whh1, bih1, bhh1,
                                      Wih2, Whh2, bih2, bhh2,
                                      (float*)d_out, B, T, F);
}

// round 6
// speedup vs baseline: 1.7376x; 1.3772x over previous
#include <cuda_runtime.h>

typedef unsigned long long u64;

// ---------- f32x2 packed helpers (Blackwell sm_103a) ----------
__device__ __forceinline__ u64 pk2(float lo, float hi) {
    u64 r; asm("mov.b64 %0,{%1,%2};" : "=l"(r) : "f"(lo), "f"(hi)); return r;
}
__device__ __forceinline__ void unpk2(u64 v, float& lo, float& hi) {
    asm("mov.b64 {%0,%1},%2;" : "=f"(lo), "=f"(hi) : "l"(v));
}
__device__ __forceinline__ u64 fma2(u64 a, u64 b, u64 c) {
    u64 d; asm("fma.rn.f32x2 %0,%1,%2,%3;" : "=l"(d) : "l"(a), "l"(b), "l"(c)); return d;
}
__device__ __forceinline__ u64 add2(u64 a, u64 b) {
    u64 d; asm("add.rn.f32x2 %0,%1,%2;" : "=l"(d) : "l"(a), "l"(b)); return d;
}
__device__ __forceinline__ u64 mul2(u64 a, u64 b) {
    u64 d; asm("mul.rn.f32x2 %0,%1,%2;" : "=l"(d) : "l"(a), "l"(b)); return d;
}
__device__ __forceinline__ u64 shfl64(u64 v, int m) {
    return __shfl_xor_sync(0xffffffffu, v, m);
}

// ---------- activations from PRE-SCALED inputs ----------
__device__ __forceinline__ float ex2a(float x) {
    float y; asm("ex2.approx.f32 %0,%1;" : "=f"(y) : "f"(x)); return y;
}
__device__ __forceinline__ float rcpa(float x) {
    float y; asm("rcp.approx.f32 %0,%1;" : "=f"(y) : "f"(x)); return y;
}
__device__ __forceinline__ float sigS(float s)  { return rcpa(1.0f + ex2a(s)); }
__device__ __forceinline__ float tanhS(float s) { return fmaf(2.0f, rcpa(1.0f + ex2a(s)), -1.0f); }

#define SSC (-1.4426950408889634f)   /* -log2(e)   : sigmoid pre-scale */
#define TSC (-2.8853900817779268f)   /* -2*log2(e) : tanh pre-scale    */

// One warp per batch row. Lanes 0-19: layer-1 unit j=lane, (i,f) in aif, (g,o)
// in ago, reading the h-section of smem. Lane 20: layer-2 (i,f) dot in aif over
// the c-section. Lane 21: layer-2 (g,o) dot in ago. The batched 4xEX2+4xRCP
// activation instructions therefore serve BOTH layers (MUFU/step: 20 -> 10),
// and lane 20's cloc register IS c2, updated by the same fmaf/tanh as c1.
__global__ void __launch_bounds__(128)
lstm_warp_kernel(const float* __restrict__ xin,
                 const float* __restrict__ Wih1, const float* __restrict__ Whh1,
                 const float* __restrict__ bih1, const float* __restrict__ bhh1,
                 const float* __restrict__ Wih2, const float* __restrict__ Whh2,
                 const float* __restrict__ bih2, const float* __restrict__ bhh2,
                 float* __restrict__ out, int B, int T, int F)
{
    const int w    = threadIdx.x >> 5;
    const int lane = threadIdx.x & 31;
    const int b    = blockIdx.x * 4 + w;

    // [warp][ping][0:32)=(h1,h1) dup, [32:64)=(c1,c1) dup
    __shared__ __align__(16) u64 sbuf[4][2][64];

    if (b >= B) return;

    const bool is20 = (lane == 20);
    const int  sec  = (lane < 20) ? 0 : 32;        // per-lane read section (u64 idx)
    u64* const wb   = &sbuf[w][0][0];

    // ---- per-lane weights (prescaled); default zero ----
    u64 wif[20], wgo[20];
#pragma unroll
    for (int k = 0; k < 20; k++) { wif[k] = 0ull; wgo[k] = 0ull; }
    u64 wxif = 0ull, wxgo = 0ull, bif = 0ull, bgo = 0ull;
    u64 wh2A = 0ull, wh2B = 0ull;

    if (lane < 20) {
        const int j = lane;
#pragma unroll
        for (int k = 0; k < 20; k++) {
            wif[k] = pk2(SSC * Whh1[j * 20 + k],        SSC * Whh1[(20 + j) * 20 + k]);
            wgo[k] = pk2(TSC * Whh1[(40 + j) * 20 + k], SSC * Whh1[(60 + j) * 20 + k]);
        }
        wxif = pk2(SSC * Wih1[j],      SSC * Wih1[20 + j]);
        wxgo = pk2(TSC * Wih1[40 + j], SSC * Wih1[60 + j]);
        bif  = pk2(SSC * (bih1[j] + bhh1[j]),
                   SSC * (bih1[20 + j] + bhh1[20 + j]));
        bgo  = pk2(TSC * (bih1[40 + j] + bhh1[40 + j]),
                   SSC * (bih1[60 + j] + bhh1[60 + j]));
    } else if (lane == 20) {
#pragma unroll
        for (int k = 0; k < 20; k++)
            wif[k] = pk2(SSC * Wih2[k], SSC * Wih2[20 + k]);
        bif  = pk2(SSC * (bih2[0] + bhh2[0]), SSC * (bih2[1] + bhh2[1]));
        wh2A = pk2(SSC * Whh2[0], SSC * Whh2[1]);
    } else if (lane == 21) {
#pragma unroll
        for (int k = 0; k < 20; k++)
            wgo[k] = pk2(TSC * Wih2[40 + k], SSC * Wih2[60 + k]);
        bgo  = pk2(TSC * (bih2[2] + bhh2[2]), SSC * (bih2[3] + bhh2[3]));
        wh2B = pk2(TSC * Whh2[2], SSC * Whh2[3]);
    }

    // butterfly-path L2 weights (future phase only)
    u64 uif = 0ull, ugo = 0ull;
    if (lane < 20) {
        uif = pk2(SSC * Wih2[lane],      SSC * Wih2[20 + lane]);
        ugo = pk2(TSC * Wih2[40 + lane], SSC * Wih2[60 + lane]);
    }
    const u64 wh2if = pk2(SSC * Whh2[0], SSC * Whh2[1]);
    const u64 wh2go = pk2(TSC * Whh2[2], SSC * Whh2[3]);
    const u64 b2if  = pk2(SSC * (bih2[0] + bhh2[0]), SSC * (bih2[1] + bhh2[1]));
    const u64 b2go  = pk2(TSC * (bih2[2] + bhh2[2]), SSC * (bih2[3] + bhh2[3]));

    // ---- state ----
    float cloc = 0.0f;      // lanes<20: c1(unit); lane20: c2
    float hloc = 0.0f;      // lanes<20: h1(unit); lane20: h2
    float h2b  = 0.0f;      // broadcast h2
    int   p    = 0;
    wb[lane]      = 0ull;   // h-section ping 0
    wb[32 + lane] = 0ull;   // c-section ping 0

    // ---- fused dual dot: returns packed gate pre-activations ----
    auto do_dot = [&](float x, u64& aif, u64& ago) {
        __syncwarp();
        const ulonglong2* hp = (const ulonglong2*)(wb + (p << 6) + sec);
        const ulonglong2 v0 = hp[0], v1 = hp[1], v2 = hp[2], v3 = hp[3], v4 = hp[4];
        const ulonglong2 v5 = hp[5], v6 = hp[6], v7 = hp[7], v8 = hp[8], v9 = hp[9];
        const u64 xx  = pk2(x, x);
        const u64 hh2 = pk2(h2b, h2b);
        u64 aA = fma2(wh2A, hh2, fma2(wxif, xx, bif));
        u64 gA = fma2(wh2B, hh2, fma2(wxgo, xx, bgo));
        u64 aB = mul2(wif[1], v0.y), gB = mul2(wgo[1], v0.y);
        aA = fma2(wif[0],  v0.x, aA); gA = fma2(wgo[0],  v0.x, gA);
        aB = fma2(wif[3],  v1.y, aB); gB = fma2(wgo[3],  v1.y, gB);
        aA = fma2(wif[2],  v1.x, aA); gA = fma2(wgo[2],  v1.x, gA);
        aB = fma2(wif[5],  v2.y, aB); gB = fma2(wgo[5],  v2.y, gB);
        aA = fma2(wif[4],  v2.x, aA); gA = fma2(wgo[4],  v2.x, gA);
        aB = fma2(wif[7],  v3.y, aB); gB = fma2(wgo[7],  v3.y, gB);
        aA = fma2(wif[6],  v3.x, aA); gA = fma2(wgo[6],  v3.x, gA);
        aB = fma2(wif[9],  v4.y, aB); gB = fma2(wgo[9],  v4.y, gB);
        aA = fma2(wif[8],  v4.x, aA); gA = fma2(wgo[8],  v4.x, gA);
        aB = fma2(wif[11], v5.y, aB); gB = fma2(wgo[11], v5.y, gB);
        aA = fma2(wif[10], v5.x, aA); gA = fma2(wgo[10], v5.x, gA);
        aB = fma2(wif[13], v6.y, aB); gB = fma2(wgo[13], v6.y, gB);
        aA = fma2(wif[12], v6.x, aA); gA = fma2(wgo[12], v6.x, gA);
        aB = fma2(wif[15], v7.y, aB); gB = fma2(wgo[15], v7.y, gB);
        aA = fma2(wif[14], v7.x, aA); gA = fma2(wgo[14], v7.x, gA);
        aB = fma2(wif[17], v8.y, aB); gB = fma2(wgo[17], v8.y, gB);
        aA = fma2(wif[16], v8.x, aA); gA = fma2(wgo[16], v8.x, gA);
        aB = fma2(wif[19], v9.y, aB); gB = fma2(wgo[19], v9.y, gB);
        aA = fma2(wif[18], v9.x, aA); gA = fma2(wgo[18], v9.x, gA);
        aif = add2(aA, aB);
        ago = add2(gA, gB);
    };

    auto store_state = [&]() {
        u64* sb = wb + ((p ^ 1) << 6);
        sb[lane]      = pk2(hloc, hloc);
        sb[32 + lane] = pk2(cloc, cloc);
        p ^= 1;
    };

    // simple all-lane-own update (peel / future L1 step)
    auto step_l1 = [&](float x) {
        u64 aif, ago;
        do_dot(x, aif, ago);
        float is, fs, gs, os; unpk2(aif, is, fs); unpk2(ago, gs, os);
        const float si = sigS(is), sf = sigS(fs), tg = tanhS(gs), so = sigS(os);
        cloc = fmaf(sf, cloc, si * tg);
        hloc = so * tanhS(cloc * TSC);
        store_state();
    };

    // butterfly L2 (flush / future phase); updates scalar (c2s, h2s)
    auto step_l2 = [&](float c1v, float& c2s, float& h2s) {
        const u64 cc = pk2(c1v, c1v);
        u64 pif = mul2(uif, cc), pgo = mul2(ugo, cc);
#pragma unroll
        for (int m = 16; m; m >>= 1) {
            pif = add2(pif, shfl64(pif, m));
            pgo = add2(pgo, shfl64(pgo, m));
        }
        const u64 hh = pk2(h2s, h2s);
        pif = fma2(wh2if, hh, add2(pif, b2if));
        pgo = fma2(wh2go, hh, add2(pgo, b2go));
        float i2, f2, g2, o2; unpk2(pif, i2, f2); unpk2(pgo, g2, o2);
        const float s2i = sigS(i2), s2f = sigS(f2), t2g = tanhS(g2), s2o = sigS(o2);
        c2s = fmaf(s2f, c2s, s2i * t2g);
        h2s = s2o * tanhS(c2s * TSC);
    };

    const float* xrow = xin + (size_t)b * T;
    float*       orow = out + (size_t)b * (T + F);

    // ---- peel t = 0: layer-1 only; then reset lane-20 L2 state ----
    float xn = __ldg(xrow + 1);
    step_l1(__ldg(xrow));
    if (is20) cloc = 0.0f;       // c2 starts at 0
    h2b = 0.0f;

    // ---- main loop: fused L1(t) + L2(t-1) ----
#pragma unroll 1
    for (int t = 1; t < T; t++) {
        const float x = xn;
        if (t + 1 < T) xn = __ldg(xrow + t + 1);

        u64 aif, ago;
        do_dot(x, aif, ago);

        float is, fs, gs, os; unpk2(aif, is, fs); unpk2(ago, gs, os);
        const float ei = ex2a(is), ef = ex2a(fs), eg = ex2a(gs), eo = ex2a(os);
        const float si = rcpa(1.0f + ei), sf = rcpa(1.0f + ef);
        const float tg = fmaf(2.0f, rcpa(1.0f + eg), -1.0f);
        const float so = rcpa(1.0f + eo);

        // route lane 21's (tg, so) to lane 20 (uniform-src broadcasts)
        const float tg21 = __shfl_sync(0xffffffffu, tg, 21);
        const float so21 = __shfl_sync(0xffffffffu, so, 21);

        const float cl_own = fmaf(sf, cloc, si * tg);
        const float cl_l20 = fmaf(sf, cloc, si * tg21);
        cloc = is20 ? cl_l20 : cl_own;

        const float tl = tanhS(cloc * TSC);
        hloc = (is20 ? so21 : so) * tl;

        h2b = __shfl_sync(0xffffffffu, hloc, 20);
        store_state();
        if (is20) orow[t - 1] = cloc;      // c2 for step t-1
    }

    // ---- extract scalar L2 state; flush L2(T-1) via butterfly ----
    float c2s = __shfl_sync(0xffffffffu, cloc, 20);
    float h2s = __shfl_sync(0xffffffffu, hloc, 20);
    step_l2(cloc, c2s, h2s);               // cloc = per-lane c1(T-1)
    if (lane == 0) orow[T - 1] = c2s;

    // ---- autoregressive future: strictly sequential ----
#pragma unroll 1
    for (int f = 0; f < F; f++) {
        step_l1(c2s);                       // lanes>=20 results ignored
        step_l2(cloc, c2s, h2s);
        if (lane == 0) orow[T + f] = c2s;
    }
}

extern "C" void kernel_launch(void* const* d_in, const int* in_sizes, int n_in,
                              void* d_out, int out_size)
{
    const float* xin  = (const float*)d_in[0];
    const float* Wih1 = (const float*)d_in[1];
    const float* Whh1 = (const float*)d_in[2];
    const float* bih1 = (const float*)d_in[3];
    const float* bhh1 = (const float*)d_in[4];
    const float* Wih2 = (const float*)d_in[5];
    const float* Whh2 = (const float*)d_in[6];
    const float* bih2 = (const float*)d_in[7];
    const float* bhh2 = (const float*)d_in[8];

    const int B = 1024;
    const int T = in_sizes[0] / B;          // 4096
    const int F = out_size / B - T;         // 16

    dim3 grid((B + 3) / 4), block(128);
    lstm_warp_kernel<<<grid, block>>>(xin, Wih1, Whh1, bih1, bhh1,
                                      Wih2, Whh2, bih2, bhh2,
                                      (float*)d_out, B, T, F);
}

// round 7
// speedup vs baseline: 1.8467x; 1.0627x over previous
#include <cuda_runtime.h>

typedef unsigned long long u64;

// ---------- f32x2 packed helpers (Blackwell sm_103a) ----------
__device__ __forceinline__ u64 pk2(float lo, float hi) {
    u64 r; asm("mov.b64 %0,{%1,%2};" : "=l"(r) : "f"(lo), "f"(hi)); return r;
}
__device__ __forceinline__ void unpk2(u64 v, float& lo, float& hi) {
    asm("mov.b64 {%0,%1},%2;" : "=f"(lo), "=f"(hi) : "l"(v));
}
__device__ __forceinline__ u64 fma2(u64 a, u64 b, u64 c) {
    u64 d; asm("fma.rn.f32x2 %0,%1,%2,%3;" : "=l"(d) : "l"(a), "l"(b), "l"(c)); return d;
}
__device__ __forceinline__ u64 add2(u64 a, u64 b) {
    u64 d; asm("add.rn.f32x2 %0,%1,%2;" : "=l"(d) : "l"(a), "l"(b)); return d;
}
__device__ __forceinline__ u64 mul2(u64 a, u64 b) {
    u64 d; asm("mul.rn.f32x2 %0,%1,%2;" : "=l"(d) : "l"(a), "l"(b)); return d;
}
__device__ __forceinline__ u64 shfl64(u64 v, int m) {
    return __shfl_xor_sync(0xffffffffu, v, m);
}

// ---------- activations ----------
__device__ __forceinline__ float ex2a(float x) {
    float y; asm("ex2.approx.f32 %0,%1;" : "=f"(y) : "f"(x)); return y;
}
__device__ __forceinline__ float rcpa(float x) {
    float y; asm("rcp.approx.f32 %0,%1;" : "=f"(y) : "f"(x)); return y;
}
#define SSC (-1.4426950408889634f)    /* -log2(e)    : sigmoid pre-scale  */
#define TSC (-2.8853900817779268f)    /* -2*log2(e)  : tanh pre-scale     */
#define INV_TSC (-0.3465735902799726f)/* 1/TSC                            */

// sigmoid from prescaled input s = SSC*x
__device__ __forceinline__ float sigS(float s)  { return rcpa(1.0f + ex2a(s)); }
// tanh from prescaled input s = TSC*x
__device__ __forceinline__ float tanhU(float s) { return fmaf(2.0f, rcpa(1.0f + ex2a(s)), -1.0f); }
// TSC*tanh(x) from prescaled input s = TSC*x   (scale folded into constants)
__device__ __forceinline__ float tanhT(float s) { return fmaf(2.0f * TSC, rcpa(1.0f + ex2a(s)), -TSC); }

// One warp per batch row. cloc is carried PRE-SCALED by TSC on all lanes.
// Lanes 0-19 : layer-1 unit j = lane; aif=(i,f), ago=(g,o) dots over h-section.
// Lane 20    : ALL FOUR layer-2 gates — aif=(i2,f2) via wif, ago=(g2,o2) via
//              wgo, both dots over the c-section (prev step's TSC*c1, weights
//              pre-divided by TSC). Its hloc IS h2; its cloc IS TSC*c2.
// Main loop: no SHFL, no lane branches — one SIMD body + predicated store.
__global__ void __launch_bounds__(128)
lstm_warp_kernel(const float* __restrict__ xin,
                 const float* __restrict__ Wih1, const float* __restrict__ Whh1,
                 const float* __restrict__ bih1, const float* __restrict__ bhh1,
                 const float* __restrict__ Wih2, const float* __restrict__ Whh2,
                 const float* __restrict__ bih2, const float* __restrict__ bhh2,
                 float* __restrict__ out, int B, int T, int F)
{
    const int w    = threadIdx.x >> 5;
    const int lane = threadIdx.x & 31;
    const int b    = blockIdx.x * 4 + w;

    // [warp][ping][0:32)=(h,h) dup, [32:64)=(TSC*c, TSC*c) dup
    __shared__ __align__(16) u64 sbuf[4][2][64];

    if (b >= B) return;

    const bool is20 = (lane == 20);
    const int  sec  = (lane < 20) ? 0 : 32;
    u64* const wb   = &sbuf[w][0][0];

    // ---- per-lane weights (prescaled); default zero ----
    u64 wif[20], wgo[20];
#pragma unroll
    for (int k = 0; k < 20; k++) { wif[k] = 0ull; wgo[k] = 0ull; }
    u64 wxif = 0ull, wxgo = 0ull, bif = 0ull, bgo = 0ull;
    u64 wh2A = 0ull, wh2B = 0ull;

    if (lane < 20) {
        const int j = lane;
#pragma unroll
        for (int k = 0; k < 20; k++) {
            wif[k] = pk2(SSC * Whh1[j * 20 + k],        SSC * Whh1[(20 + j) * 20 + k]);
            wgo[k] = pk2(TSC * Whh1[(40 + j) * 20 + k], SSC * Whh1[(60 + j) * 20 + k]);
        }
        wxif = pk2(SSC * Wih1[j],      SSC * Wih1[20 + j]);
        wxgo = pk2(TSC * Wih1[40 + j], SSC * Wih1[60 + j]);
        bif  = pk2(SSC * (bih1[j] + bhh1[j]),
                   SSC * (bih1[20 + j] + bhh1[20 + j]));
        bgo  = pk2(TSC * (bih1[40 + j] + bhh1[40 + j]),
                   SSC * (bih1[60 + j] + bhh1[60 + j]));
    } else if (lane == 20) {
        // L2 dots read TSC*c1 -> fold 1/TSC into the weights
#pragma unroll
        for (int k = 0; k < 20; k++) {
            wif[k] = pk2(SSC * INV_TSC * Wih2[k],      SSC * INV_TSC * Wih2[20 + k]);
            wgo[k] = pk2(Wih2[40 + k],                 SSC * INV_TSC * Wih2[60 + k]);
        }
        bif  = pk2(SSC * (bih2[0] + bhh2[0]), SSC * (bih2[1] + bhh2[1]));
        bgo  = pk2(TSC * (bih2[2] + bhh2[2]), SSC * (bih2[3] + bhh2[3]));
        wh2A = pk2(SSC * Whh2[0], SSC * Whh2[1]);   // h2 in normal units (own hloc)
        wh2B = pk2(TSC * Whh2[2], SSC * Whh2[3]);
    }

    // butterfly-path L2 weights (flush / future phase only); input is TSC*c1
    u64 uif = 0ull, ugo = 0ull;
    if (lane < 20) {
        uif = pk2(SSC * INV_TSC * Wih2[lane],  SSC * INV_TSC * Wih2[20 + lane]);
        ugo = pk2(Wih2[40 + lane],             SSC * INV_TSC * Wih2[60 + lane]);
    }
    const u64 wh2if = pk2(SSC * Whh2[0], SSC * Whh2[1]);
    const u64 wh2go = pk2(TSC * Whh2[2], SSC * Whh2[3]);
    const u64 b2if  = pk2(SSC * (bih2[0] + bhh2[0]), SSC * (bih2[1] + bhh2[1]));
    const u64 b2go  = pk2(TSC * (bih2[2] + bhh2[2]), SSC * (bih2[3] + bhh2[3]));

    // ---- state ----
    float cloc = 0.0f;      // lanes<20: TSC*c1(unit); lane20: TSC*c2
    float hloc = 0.0f;      // lanes<20: h1(unit);     lane20: h2
    int   p    = 0;
    wb[lane]      = 0ull;
    wb[32 + lane] = 0ull;

    // ---- one fused SIMD step: identical on every lane ----
    auto step = [&](float x) {
        __syncwarp();
        const ulonglong2* hp = (const ulonglong2*)(wb + (p << 6) + sec);
        const ulonglong2 v0 = hp[0], v1 = hp[1], v2 = hp[2], v3 = hp[3], v4 = hp[4];
        const ulonglong2 v5 = hp[5], v6 = hp[6], v7 = hp[7], v8 = hp[8], v9 = hp[9];
        const u64 xx = pk2(x, x);
        const u64 hh = pk2(hloc, hloc);          // lane-local: h1 (zero-wt) or h2
        u64 aA = fma2(wh2A, hh, fma2(wxif, xx, bif));
        u64 gA = fma2(wh2B, hh, fma2(wxgo, xx, bgo));
        u64 aB = mul2(wif[1], v0.y), gB = mul2(wgo[1], v0.y);
        aA = fma2(wif[0],  v0.x, aA); gA = fma2(wgo[0],  v0.x, gA);
        aB = fma2(wif[3],  v1.y, aB); gB = fma2(wgo[3],  v1.y, gB);
        aA = fma2(wif[2],  v1.x, aA); gA = fma2(wgo[2],  v1.x, gA);
        aB = fma2(wif[5],  v2.y, aB); gB = fma2(wgo[5],  v2.y, gB);
        aA = fma2(wif[4],  v2.x, aA); gA = fma2(wgo[4],  v2.x, gA);
        aB = fma2(wif[7],  v3.y, aB); gB = fma2(wgo[7],  v3.y, gB);
        aA = fma2(wif[6],  v3.x, aA); gA = fma2(wgo[6],  v3.x, gA);
        aB = fma2(wif[9],  v4.y, aB); gB = fma2(wgo[9],  v4.y, gB);
        aA = fma2(wif[8],  v4.x, aA); gA = fma2(wgo[8],  v4.x, gA);
        aB = fma2(wif[11], v5.y, aB); gB = fma2(wgo[11], v5.y, gB);
        aA = fma2(wif[10], v5.x, aA); gA = fma2(wgo[10], v5.x, gA);
        aB = fma2(wif[13], v6.y, aB); gB = fma2(wgo[13], v6.y, gB);
        aA = fma2(wif[12], v6.x, aA); gA = fma2(wgo[12], v6.x, gA);
        aB = fma2(wif[15], v7.y, aB); gB = fma2(wgo[15], v7.y, gB);
        aA = fma2(wif[14], v7.x, aA); gA = fma2(wgo[14], v7.x, gA);
        aB = fma2(wif[17], v8.y, aB); gB = fma2(wgo[17], v8.y, gB);
        aA = fma2(wif[16], v8.x, aA); gA = fma2(wgo[16], v8.x, gA);
        aB = fma2(wif[19], v9.y, aB); gB = fma2(wgo[19], v9.y, gB);
        aA = fma2(wif[18], v9.x, aA); gA = fma2(wgo[18], v9.x, gA);
        const u64 aif = add2(aA, aB), ago = add2(gA, gB);

        float is, fs, gs, os; unpk2(aif, is, fs); unpk2(ago, gs, os);
        const float ei = ex2a(is), ef = ex2a(fs), eg = ex2a(gs), eo = ex2a(os);
        const float si = rcpa(1.0f + ei), sf = rcpa(1.0f + ef);
        const float tgT = fmaf(2.0f * TSC, rcpa(1.0f + eg), -TSC);  // TSC*tanh
        const float so = rcpa(1.0f + eo);

        cloc = fmaf(sf, cloc, si * tgT);         // TSC-scaled c update
        hloc = so * tanhU(cloc);                 // EX2 directly on scaled c

        u64* sb = wb + ((p ^ 1) << 6);
        sb[lane]      = pk2(hloc, hloc);
        sb[32 + lane] = pk2(cloc, cloc);
        p ^= 1;
    };

    // ---- butterfly L2 (flush / future phase); c1v is TSC-scaled ----
    auto step_l2 = [&](float c1v, float& c2s, float& h2s) {
        const u64 cc = pk2(c1v, c1v);
        u64 pif = mul2(uif, cc), pgo = mul2(ugo, cc);
#pragma unroll
        for (int m = 16; m; m >>= 1) {
            pif = add2(pif, shfl64(pif, m));
            pgo = add2(pgo, shfl64(pgo, m));
        }
        const u64 hh = pk2(h2s, h2s);
        pif = fma2(wh2if, hh, add2(pif, b2if));
        pgo = fma2(wh2go, hh, add2(pgo, b2go));
        float i2, f2, g2, o2; unpk2(pif, i2, f2); unpk2(pgo, g2, o2);
        const float s2i = sigS(i2), s2f = sigS(f2), t2g = tanhU(g2), s2o = sigS(o2);
        c2s = fmaf(s2f, c2s, s2i * t2g);
        h2s = s2o * tanhU(c2s * TSC);
    };

    const float* xrow = xin + (size_t)b * T;
    float*       orow = out + (size_t)b * (T + F);

    // ---- peel t = 0: L1 only; reset lane-20's (garbage) L2 state ----
    float xn = __ldg(xrow + 1);
    step(__ldg(xrow));
    if (is20) { cloc = 0.0f; hloc = 0.0f; }

    // ---- main loop: fused L1(t) + L2(t-1), zero shuffles ----
#pragma unroll 1
    for (int t = 1; t < T; t++) {
        const float x = xn;
        if (t + 1 < T) xn = __ldg(xrow + t + 1);
        step(x);
        if (is20) orow[t - 1] = cloc * INV_TSC;   // c2(t-1)
    }

    // ---- flush: L2 for step T-1 via butterfly ----
    float c2s = __shfl_sync(0xffffffffu, cloc, 20) * INV_TSC;
    float h2s = __shfl_sync(0xffffffffu, hloc, 20);
    step_l2(cloc, c2s, h2s);                      // cloc = TSC*c1(T-1)
    if (lane == 0) orow[T - 1] = c2s;

    // ---- autoregressive future: strictly sequential ----
#pragma unroll 1
    for (int f = 0; f < F; f++) {
        step(c2s);                                 // lanes>=20 results unused
        step_l2(cloc, c2s, h2s);
        if (lane == 0) orow[T + f] = c2s;
    }
}

extern "C" void kernel_launch(void* const* d_in, const int* in_sizes, int n_in,
                              void* d_out, int out_size)
{
    const float* xin  = (const float*)d_in[0];
    const float* Wih1 = (const float*)d_in[1];
    const float* Whh1 = (const float*)d_in[2];
    const float* bih1 = (const float*)d_in[3];
    const float* bhh1 = (const float*)d_in[4];
    const float* Wih2 = (const float*)d_in[5];
    const float* Whh2 = (const float*)d_in[6];
    const float* bih2 = (const float*)d_in[7];
    const float* bhh2 = (const float*)d_in[8];

    const int B = 1024;
    const int T = in_sizes[0] / B;          // 4096
    const int F = out_size / B - T;         // 16

    dim3 grid((B + 3) / 4), block(128);
    lstm_warp_kernel<<<grid, block>>>(xin, Wih1, Whh1, bih1, bhh1,
                                      Wih2, Whh2, bih2, bhh2,
                                      (float*)d_out, B, T, F);
}